// round 1
// baseline (speedup 1.0000x reference)
#include <cuda_runtime.h>
#include <cuda_bf16.h>
#include <cstdint>

// LRML: out[b] = -|| ue + rel - ie ||^2
//   ue = renorm(user_emb[user_ids[b]]), ie = renorm(item_emb[item_ids[b]])
//   joint = ue*ie ; scores = softmax(joint @ W_att^T)  [M=10]
//   rel = scores @ memory
//
// One warp per batch row; lane = dimension d (D == 32 == warpSize).
// W_att and memory (10x32 each) staged in shared memory per block.

#define D 32
#define M 10
#define WARPS_PER_BLOCK 8
#define THREADS (WARPS_PER_BLOCK * 32)

__device__ __forceinline__ float warp_sum(float v) {
    #pragma unroll
    for (int ofs = 16; ofs > 0; ofs >>= 1)
        v += __shfl_xor_sync(0xFFFFFFFFu, v, ofs);
    return v;
}

__global__ __launch_bounds__(THREADS)
void lrml_kernel(const int* __restrict__ user_ids,
                 const int* __restrict__ item_ids,
                 const float* __restrict__ user_emb,
                 const float* __restrict__ item_emb,
                 const float* __restrict__ W_att,
                 const float* __restrict__ memory,
                 float* __restrict__ out,
                 int B)
{
    __shared__ float sW[M * D];
    __shared__ float sMem[M * D];

    // Stage the tiny weight matrices (320 floats each)
    for (int i = threadIdx.x; i < M * D; i += THREADS) {
        sW[i]   = W_att[i];
        sMem[i] = memory[i];
    }
    __syncthreads();

    const int warp_id = threadIdx.x >> 5;
    const int lane    = threadIdx.x & 31;
    const int row     = blockIdx.x * WARPS_PER_BLOCK + warp_id;
    if (row >= B) return;

    const int uid = user_ids[row];
    const int iid = item_ids[row];

    // Coalesced gather: one 128B line per embedding row
    float ue = __ldg(&user_emb[(size_t)uid * D + lane]);
    float ie = __ldg(&item_emb[(size_t)iid * D + lane]);

    // max_norm=1 renormalization: e *= 1/max(||e||, 1)
    float un = sqrtf(warp_sum(ue * ue));
    float in = sqrtf(warp_sum(ie * ie));
    ue *= (un > 1.0f) ? (1.0f / un) : 1.0f;
    ie *= (in > 1.0f) ? (1.0f / in) : 1.0f;

    const float joint = ue * ie;

    // scores[m] = joint . W_att[m]  (every lane ends with all M sums)
    float s[M];
    #pragma unroll
    for (int m = 0; m < M; m++)
        s[m] = warp_sum(joint * sW[m * D + lane]);

    // softmax over M=10 in registers
    float mx = s[0];
    #pragma unroll
    for (int m = 1; m < M; m++) mx = fmaxf(mx, s[m]);
    float denom = 0.0f;
    #pragma unroll
    for (int m = 0; m < M; m++) { s[m] = __expf(s[m] - mx); denom += s[m]; }
    const float inv_denom = 1.0f / denom;

    // rel[d] = sum_m softmax(s)[m] * memory[m][d]
    float rel = 0.0f;
    #pragma unroll
    for (int m = 0; m < M; m++)
        rel = fmaf(s[m], sMem[m * D + lane], rel);
    rel *= inv_denom;

    const float diff = ue + rel - ie;
    const float dist = warp_sum(diff * diff);

    if (lane == 0) out[row] = -dist;
}

extern "C" void kernel_launch(void* const* d_in, const int* in_sizes, int n_in,
                              void* d_out, int out_size)
{
    const int*   user_ids = (const int*)  d_in[0];
    const int*   item_ids = (const int*)  d_in[1];
    const float* user_emb = (const float*)d_in[2];
    const float* item_emb = (const float*)d_in[3];
    const float* W_att    = (const float*)d_in[4];
    const float* memory   = (const float*)d_in[5];
    float*       out      = (float*)d_out;

    const int B = in_sizes[0];
    const int grid = (B + WARPS_PER_BLOCK - 1) / WARPS_PER_BLOCK;
    lrml_kernel<<<grid, THREADS>>>(user_ids, item_ids, user_emb, item_emb,
                                   W_att, memory, out, B);
}

// round 3
// speedup vs baseline: 1.9375x; 1.9375x over previous
#include <cuda_runtime.h>
#include <cuda_bf16.h>
#include <cstdint>

// LRML: out[b] = -|| ue + rel - ie ||^2
// Layout: 4 lanes per batch row (quad), each lane owns 8 of D=32 dims
// via two float4 loads. Reductions are 2 shfl_xor (offsets 1,2) inside
// the quad. One warp handles 8 rows -> ~20x fewer SHFLs than 1-warp/row.

#define D 32
#define M 10
#define LANES_PER_ROW 4
#define ROWS_PER_WARP 8
#define WARPS_PER_BLOCK 8
#define THREADS (WARPS_PER_BLOCK * 32)
#define ROWS_PER_BLOCK (WARPS_PER_BLOCK * ROWS_PER_WARP)

__device__ __forceinline__ float quad_sum(float v) {
    v += __shfl_xor_sync(0xFFFFFFFFu, v, 1);
    v += __shfl_xor_sync(0xFFFFFFFFu, v, 2);
    return v;
}

__global__ __launch_bounds__(THREADS)
void lrml_kernel(const int* __restrict__ user_ids,
                 const int* __restrict__ item_ids,
                 const float* __restrict__ user_emb,
                 const float* __restrict__ item_emb,
                 const float* __restrict__ W_att,
                 const float* __restrict__ memory,
                 float* __restrict__ out,
                 int B)
{
    __shared__ float4 sW[M * 8];    // W_att  rows as float4 (10 x 32 floats)
    __shared__ float4 sMem[M * 8];  // memory rows as float4

    for (int i = threadIdx.x; i < M * 8; i += THREADS) {
        sW[i]   = ((const float4*)W_att)[i];
        sMem[i] = ((const float4*)memory)[i];
    }
    __syncthreads();

    const int lane = threadIdx.x & 31;
    const int q    = lane & 3;        // quad-local: which 8-dim slice
    const int r    = lane >> 2;       // row within warp (0..7)
    const int warp = threadIdx.x >> 5;
    const int row  = blockIdx.x * ROWS_PER_BLOCK + warp * ROWS_PER_WARP + r;
    if (row >= B) return;

    const int uid = __ldg(&user_ids[row]);
    const int iid = __ldg(&item_ids[row]);

    // Each lane: 8 contiguous floats (two float4) of its row.
    const float4* up = (const float4*)(user_emb + (size_t)uid * D + q * 8);
    const float4* ip = (const float4*)(item_emb + (size_t)iid * D + q * 8);
    float4 u0 = __ldg(up);
    float4 u1 = __ldg(up + 1);
    float4 i0 = __ldg(ip);
    float4 i1 = __ldg(ip + 1);

    float ue[8] = {u0.x,u0.y,u0.z,u0.w, u1.x,u1.y,u1.z,u1.w};
    float ie[8] = {i0.x,i0.y,i0.z,i0.w, i1.x,i1.y,i1.z,i1.w};

    // max_norm=1 renorm
    float us = 0.f, is = 0.f;
    #pragma unroll
    for (int j = 0; j < 8; j++) { us = fmaf(ue[j], ue[j], us); is = fmaf(ie[j], ie[j], is); }
    us = quad_sum(us);
    is = quad_sum(is);
    const float un = sqrtf(us), in = sqrtf(is);
    const float uscale = (un > 1.0f) ? (1.0f / un) : 1.0f;
    const float iscale = (in > 1.0f) ? (1.0f / in) : 1.0f;
    #pragma unroll
    for (int j = 0; j < 8; j++) { ue[j] *= uscale; ie[j] *= iscale; }

    float joint[8];
    #pragma unroll
    for (int j = 0; j < 8; j++) joint[j] = ue[j] * ie[j];

    // scores[m] = joint . W_att[m], reduced over the quad
    float s[M];
    #pragma unroll
    for (int m = 0; m < M; m++) {
        float4 w0 = sW[m * 8 + q * 2];
        float4 w1 = sW[m * 8 + q * 2 + 1];
        float p = joint[0] * w0.x;
        p = fmaf(joint[1], w0.y, p);
        p = fmaf(joint[2], w0.z, p);
        p = fmaf(joint[3], w0.w, p);
        p = fmaf(joint[4], w1.x, p);
        p = fmaf(joint[5], w1.y, p);
        p = fmaf(joint[6], w1.z, p);
        p = fmaf(joint[7], w1.w, p);
        s[m] = quad_sum(p);
    }

    // softmax over M=10 (all lanes of the quad hold identical s[])
    float mx = s[0];
    #pragma unroll
    for (int m = 1; m < M; m++) mx = fmaxf(mx, s[m]);
    float denom = 0.0f;
    #pragma unroll
    for (int m = 0; m < M; m++) { s[m] = __expf(s[m] - mx); denom += s[m]; }
    const float inv_denom = 1.0f / denom;
    #pragma unroll
    for (int m = 0; m < M; m++) s[m] *= inv_denom;

    // rel[j] = sum_m s[m] * memory[m][q*8+j]
    float rel[8] = {0,0,0,0,0,0,0,0};
    #pragma unroll
    for (int m = 0; m < M; m++) {
        float4 m0 = sMem[m * 8 + q * 2];
        float4 m1 = sMem[m * 8 + q * 2 + 1];
        rel[0] = fmaf(s[m], m0.x, rel[0]);
        rel[1] = fmaf(s[m], m0.y, rel[1]);
        rel[2] = fmaf(s[m], m0.z, rel[2]);
        rel[3] = fmaf(s[m], m0.w, rel[3]);
        rel[4] = fmaf(s[m], m1.x, rel[4]);
        rel[5] = fmaf(s[m], m1.y, rel[5]);
        rel[6] = fmaf(s[m], m1.z, rel[6]);
        rel[7] = fmaf(s[m], m1.w, rel[7]);
    }

    float dist = 0.0f;
    #pragma unroll
    for (int j = 0; j < 8; j++) {
        const float diff = ue[j] + rel[j] - ie[j];
        dist = fmaf(diff, diff, dist);
    }
    dist = quad_sum(dist);

    if (q == 0) out[row] = -dist;
}

extern "C" void kernel_launch(void* const* d_in, const int* in_sizes, int n_in,
                              void* d_out, int out_size)
{
    const int*   user_ids = (const int*)  d_in[0];
    const int*   item_ids = (const int*)  d_in[1];
    const float* user_emb = (const float*)d_in[2];
    const float* item_emb = (const float*)d_in[3];
    const float* W_att    = (const float*)d_in[4];
    const float* memory   = (const float*)d_in[5];
    float*       out      = (float*)d_out;

    const int B = in_sizes[0];
    const int grid = (B + ROWS_PER_BLOCK - 1) / ROWS_PER_BLOCK;
    lrml_kernel<<<grid, THREADS>>>(user_ids, item_ids, user_emb, item_emb,
                                   W_att, memory, out, B);
}